// round 9
// baseline (speedup 1.0000x reference)
#include <cuda_runtime.h>

#define G        64
#define IMGSZ    512
#define NTHREADS 1024

#define EDGE_SCALE (1.0f / 0.875f)   // all patch-edge wsums are 7/8

// tmp region: 4224 floats (16896 B). raw region: 68 rows * 272 floats.
#define TMP_FLOATS 4224
#define RSTR4 272
#define RSTR2 136

__device__ __forceinline__ float ldimg(const float* __restrict__ img, int gy, int gx) {
    if ((unsigned)gy < IMGSZ && (unsigned)gx < IMGSZ)
        return __ldg(img + gy * IMGSZ + gx);
    return 0.0f;
}

__device__ __forceinline__ void cpasync16(float* dst, const float* src) {
    unsigned d = (unsigned)__cvta_generic_to_shared(dst);
    asm volatile("cp.async.cg.shared.global [%0], [%1], 16;\n" :: "r"(d), "l"(src));
}
__device__ __forceinline__ void cpasync_drain() {
    asm volatile("cp.async.commit_group;\n" ::: "memory");
    asm volatile("cp.async.wait_group 0;\n" ::: "memory");
}

// ======================= S = 4 (img4 -> window 2) =======================
// Raw patch rows staged to smem via cp.async (zero-filled where invalid),
// then vertical triangle filter [1,3,5,7,7,5,3,1]/32 (branch-free), then
// horizontal from aligned float4 chunks. out_y = s_y + t_{y+1}; outputs
// y==0/63 and i==0/63 scaled by EDGE_SCALE (excluded-tap renorm).
__device__ void ds4_slice(const float* __restrict__ img, float* __restrict__ o,
                          int by, int bx, int y0, float* __restrict__ smem) {
    float* tmp = smem;                 // [16][264], col j at +2, pads zeroed
    float* raw = smem + TMP_FLOATS;    // [68][RSTR4]
    const int tid = threadIdx.x;

    // geometry (uniform per block)
    const int cl = max(bx, 0);
    const int cr = min(bx + 256, IMGSZ);
    const int A  = cl & ~3;                 // 16B-aligned gmem start col
    const int nq = (cr - A + 3) >> 2;       // float4s per row (<=65)
    const int d  = bx - A;                  // patch col j -> raw idx j + d  (valid gx only)
    const int rlo = 4 * y0 - 2;

    // ---- stage 68 rows of the patch slice ----
    const int total = 68 * nq;
    for (int it = tid; it < total; it += NTHREADS) {
        int lr = it / nq;
        int k  = it - lr * nq;
        int r  = rlo + lr;
        int gy = by + r;
        float* dstp = raw + lr * RSTR4 + 4 * k;
        if ((unsigned)r < 256u && (unsigned)gy < (unsigned)IMGSZ)
            cpasync16(dstp, img + (size_t)gy * IMGSZ + A + 4 * k);
        else
            *(float4*)dstp = make_float4(0.f, 0.f, 0.f, 0.f);
    }
    if (tid < 16) {                    // zero tmp pad cells
        float* rp = tmp + tid * 264;
        rp[0] = 0.f; rp[1] = 0.f; rp[258] = 0.f; rp[259] = 0.f;
    }
    cpasync_drain();
    __syncthreads();

    // ---- vertical: j = tid&255 (patch col), h = tid>>8 (4 output rows) ----
    {
        const int j  = tid & 255;
        const int h  = tid >> 8;
        const int gx = bx + j;
        if ((unsigned)gx >= (unsigned)IMGSZ) {
#pragma unroll
            for (int yy = 0; yy < 4; yy++) tmp[(4 * h + yy) * 264 + 2 + j] = 0.f;
        } else {
            const float* cb = raw + (size_t)(16 * h) * RSTR4 + (gx - A);
            const int ylo = y0 + 4 * h;
            float sp = 0.f;
#pragma unroll
            for (int cm = 0; cm <= 4; cm++) {
                float v0 = cb[(4 * cm + 0) * RSTR4];
                float v1 = cb[(4 * cm + 1) * RSTR4];
                float v2 = cb[(4 * cm + 2) * RSTR4];
                float v3 = cb[(4 * cm + 3) * RSTR4];
                float s = fmaf(7.f/32, v3, fmaf(5.f/32, v2, fmaf(3.f/32, v1, (1.f/32)*v0)));
                float t = fmaf(1.f/32, v3, fmaf(3.f/32, v2, fmaf(5.f/32, v1, (7.f/32)*v0)));
                if (cm > 0) {
                    int y = ylo + cm - 1;
                    float raww = sp + t;
                    if (y == 0 || y == 63) raww *= EDGE_SCALE;
                    tmp[(4 * h + cm - 1) * 264 + 2 + j] = raww;
                }
                sp = s;
            }
        }
    }
    __syncthreads();

    // ---- horizontal from smem, aligned float4 chunks ----
    const float4* t4 = (const float4*)tmp;   // row stride 66 float4s
    {
        int idx = tid;                        // 16*64 == NTHREADS
        int yy = idx >> 6, i = idx & 63;
        float4 a = t4[yy * 66 + i];
        float4 b = t4[yy * 66 + i + 1];
        float acc = (1.f/32)*a.x + (3.f/32)*a.y + (5.f/32)*a.z + (7.f/32)*a.w
                  + (7.f/32)*b.x + (5.f/32)*b.y + (3.f/32)*b.z + (1.f/32)*b.w;
        if (i == 0 || i == 63) acc *= EDGE_SCALE;
        o[(y0 + yy) * G + i] = acc;
    }
}

// ======================= S = 2 (img2 -> window 1) =======================
// Weights [1,3,3,1]/8; s=[1,3]/8, t=[3,1]/8 per 2-row chunk.
__device__ void ds2_slice(const float* __restrict__ img, float* __restrict__ o,
                          int by, int bx, int y0, float* __restrict__ smem) {
    float* tmp = smem;                 // [32][132], col j at +1, pads zeroed
    float* raw = smem + TMP_FLOATS;    // [66][RSTR2]
    const int tid = threadIdx.x;

    const int cl = max(bx, 0);
    const int cr = min(bx + 128, IMGSZ);
    const int A  = cl & ~3;
    const int nq = (cr - A + 3) >> 2;       // <=33
    const int rlo = 2 * y0 - 1;

    const int total = 66 * nq;
    for (int it = tid; it < total; it += NTHREADS) {
        int lr = it / nq;
        int k  = it - lr * nq;
        int r  = rlo + lr;
        int gy = by + r;
        float* dstp = raw + lr * RSTR2 + 4 * k;
        if ((unsigned)r < 128u && (unsigned)gy < (unsigned)IMGSZ)
            cpasync16(dstp, img + (size_t)gy * IMGSZ + A + 4 * k);
        else
            *(float4*)dstp = make_float4(0.f, 0.f, 0.f, 0.f);
    }
    if (tid < 32) {                    // zero tmp pad cells
        float* rp = tmp + tid * 132;
        rp[0] = 0.f; rp[129] = 0.f;
    }
    cpasync_drain();
    __syncthreads();

    // ---- vertical: j = tid&127 (col), h = tid>>7 (4 output rows each) ----
    {
        const int j  = tid & 127;
        const int h  = tid >> 7;            // 0..7
        const int gx = bx + j;
        if ((unsigned)gx >= (unsigned)IMGSZ) {
#pragma unroll
            for (int yy = 0; yy < 4; yy++) tmp[(4 * h + yy) * 132 + 1 + j] = 0.f;
        } else {
            const float* cb = raw + (size_t)(8 * h) * RSTR2 + (gx - A);
            const int ylo = y0 + 4 * h;
            float sp = 0.f;
#pragma unroll
            for (int cm = 0; cm <= 4; cm++) {
                float v0 = cb[(2 * cm + 0) * RSTR2];
                float v1 = cb[(2 * cm + 1) * RSTR2];
                float s = fmaf(3.f/8, v1, (1.f/8)*v0);
                float t = fmaf(1.f/8, v1, (3.f/8)*v0);
                if (cm > 0) {
                    int y = ylo + cm - 1;
                    float raww = sp + t;
                    if (y == 0 || y == 63) raww *= EDGE_SCALE;
                    tmp[(4 * h + cm - 1) * 132 + 1 + j] = raww;
                }
                sp = s;
            }
        }
    }
    __syncthreads();

    // ---- horizontal from smem, aligned float2 chunks ----
    const float2* t2 = (const float2*)tmp;   // row stride 66 float2s
#pragma unroll
    for (int u = 0; u < 2; u++) {
        int idx = tid + u * NTHREADS;        // 32*64 = 2048
        int yy = idx >> 6, i = idx & 63;
        float2 a = t2[yy * 66 + i];
        float2 b = t2[yy * 66 + i + 1];
        float acc = (1.f/8)*a.x + (3.f/8)*a.y + (3.f/8)*b.x + (1.f/8)*b.y;
        if (i == 0 || i == 63) acc *= EDGE_SCALE;
        o[(y0 + yy) * G + i] = acc;
    }
}

// Grid (1344 blocks), heavy work first:
//   [0, 768)     : S=4, 4 slices x 16 rows per (b,c)
//   [768, 1152)  : S=2, 2 slices x 32 rows per (b,c)
//   [1152, 1344) : direct 64x64 zero-padded crop of img0
__global__ __launch_bounds__(NTHREADS, 2)
void glimpse_kernel(const float* __restrict__ img0,
                    const float* __restrict__ img2,
                    const float* __restrict__ img4,
                    const float* __restrict__ loc,
                    float* __restrict__ out) {
    extern __shared__ __align__(16) float smem[];

    int blk = blockIdx.x;
    int sel, bc, slice;
    if (blk < 768)       { sel = 0; bc = blk >> 2;          slice = blk & 3; }
    else if (blk < 1152) { sel = 1; bc = (blk - 768) >> 1;  slice = (blk - 768) & 1; }
    else                 { sel = 2; bc = blk - 1152;        slice = 0; }
    int b = bc / 3;
    int c = bc - b * 3;

    // start index, matching jnp: trunc(0.5f * ((loc + 1.0f) * 511.0f))
    float lx = loc[2 * b + 0];
    float ly = loc[2 * b + 1];
    int sx = (int)(0.5f * ((lx + 1.0f) * 511.0f));
    int sy = (int)(0.5f * ((ly + 1.0f) * 511.0f));

    if (sel == 0) {
        const float* img = img4 + (size_t)(b * 3 + c) * IMGSZ * IMGSZ;
        float* o = out + (size_t)((b * 3 + 2) * 3 + c) * G * G;
        ds4_slice(img, o, sy - 128, sx - 128, slice * 16, smem);
    } else if (sel == 1) {
        const float* img = img2 + (size_t)(b * 3 + c) * IMGSZ * IMGSZ;
        float* o = out + (size_t)((b * 3 + 1) * 3 + c) * G * G;
        ds2_slice(img, o, sy - 64, sx - 64, slice * 32, smem);
    } else {
        const float* img = img0 + (size_t)(b * 3 + c) * IMGSZ * IMGSZ;
        float* o = out + (size_t)((b * 3 + 0) * 3 + c) * G * G;
        int by = sy - G / 2, bx = sx - G / 2;
        for (int idx = threadIdx.x; idx < G * G; idx += NTHREADS) {
            int y = idx >> 6, x = idx & 63;
            o[idx] = ldimg(img, by + y, bx + x);
        }
    }
}

extern "C" void kernel_launch(void* const* d_in, const int* in_sizes, int n_in,
                              void* d_out, int out_size) {
    const float* img0 = (const float*)d_in[0];
    const float* img2 = (const float*)d_in[1];
    const float* img4 = (const float*)d_in[2];
    const float* loc  = (const float*)d_in[3];
    float* out = (float*)d_out;

    // tmp (16896 B) + raw (68 * 272 * 4 = 73984 B) = 90880 B
    const size_t smem = 90880;
    cudaFuncSetAttribute(glimpse_kernel,
                         cudaFuncAttributeMaxDynamicSharedMemorySize, (int)smem);
    glimpse_kernel<<<1344, NTHREADS, smem>>>(img0, img2, img4, loc, out);
}

// round 10
// speedup vs baseline: 1.5602x; 1.5602x over previous
#include <cuda_runtime.h>

#define G        64
#define IMGSZ    512
#define CHSTRIDE (IMGSZ * IMGSZ)     // 262144 floats per channel
#define NTHREADS 512

#define EDGE_SCALE (1.0f / 0.875f)   // all patch-edge wsums are 7/8

__device__ __forceinline__ float ldimg(const float* __restrict__ img, int gy, int gx) {
    if ((unsigned)gy < IMGSZ && (unsigned)gx < IMGSZ)
        return __ldg(img + gy * IMGSZ + gx);
    return 0.0f;
}

// ======================= S = 4 (img4 -> window 2) =======================
// Vertical-first separable filter, 3 channels fused (imm-offset variants of
// one address). Weights [1,3,5,7,7,5,3,1]/32; chunk m = rows [4m-2,4m+2):
// s_m=[1,3,5,7]/32, t_m=[7,5,3,1]/32, out_y = s_y + t_{y+1}. Rows outside
// patch/image are 0; outputs y/i == 0/63 get *EDGE_SCALE.
// 8 output rows per block. tmp: [3][8][264]; col j at +2, pads zeroed, so
// horizontal chunk i is the aligned float4 at index i (row = 66 float4s).
__device__ void ds4_slice3(const float* __restrict__ imgb, float* __restrict__ ob,
                           int by, int bx, int y0, float* __restrict__ tmp) {
    const int tid = threadIdx.x;

    // zero pads: 3ch*8rows (contiguous 24 rows of 264) x cells {0,1,258,259}
    if (tid < 96) {
        int rs = tid >> 2, k = tid & 3;
        tmp[rs * 264 + ((k < 2) ? k : 256 + k)] = 0.f;
    }

    // ---- phase 1: vertical; j = tid&255 (patch col), h = tid>>8 (4 rows) ----
    {
        const int j   = tid & 255;
        const int h   = tid >> 8;          // 0..1
        const int ylo = y0 + 4 * h;
        const int gx  = bx + j;
        float* tb = tmp + (4 * h) * 264 + 2 + j;   // + ch*2112 + cm*264 (imm)
        if ((unsigned)gx >= (unsigned)IMGSZ) {
#pragma unroll
            for (int ch = 0; ch < 3; ch++)
#pragma unroll
                for (int yy = 0; yy < 4; yy++) tb[ch * 2112 + yy * 264] = 0.f;
        } else {
            const int rlo = 4 * ylo - 2;
            const bool allok = (rlo >= 0) && (rlo + 19 < 256) &&
                               (by + rlo >= 0) && (by + rlo + 19 < IMGSZ);
            float sp[3] = {0.f, 0.f, 0.f};
            if (allok) {
                const float* p = imgb + (size_t)(by + rlo) * IMGSZ + gx;
#pragma unroll
                for (int cm = 0; cm <= 4; cm++) {
#pragma unroll
                    for (int ch = 0; ch < 3; ch++) {
                        const float* q = p + ch * CHSTRIDE + 4 * cm * IMGSZ;
                        float v0 = __ldg(q);
                        float v1 = __ldg(q + IMGSZ);
                        float v2 = __ldg(q + 2 * IMGSZ);
                        float v3 = __ldg(q + 3 * IMGSZ);
                        float s = fmaf(7.f/32, v3, fmaf(5.f/32, v2, fmaf(3.f/32, v1, (1.f/32)*v0)));
                        float t = fmaf(1.f/32, v3, fmaf(3.f/32, v2, fmaf(5.f/32, v1, (7.f/32)*v0)));
                        if (cm > 0) {
                            int y = ylo + cm - 1;
                            float r = sp[ch] + t;
                            if (y == 0 || y == 63) r *= EDGE_SCALE;
                            tb[ch * 2112 + (cm - 1) * 264] = r;
                        }
                        sp[ch] = s;
                    }
                }
            } else {
#pragma unroll
                for (int cm = 0; cm <= 4; cm++) {
                    float v[3][4];
#pragma unroll
                    for (int k = 0; k < 4; k++) {
                        int r  = 4 * (ylo + cm) - 2 + k;
                        int gy = by + r;
                        bool ok = (unsigned)r < 256u && (unsigned)gy < (unsigned)IMGSZ;
                        const float* q = imgb + (size_t)(ok ? gy : 0) * IMGSZ + gx;
#pragma unroll
                        for (int ch = 0; ch < 3; ch++)
                            v[ch][k] = ok ? __ldg(q + ch * CHSTRIDE) : 0.f;
                    }
#pragma unroll
                    for (int ch = 0; ch < 3; ch++) {
                        float s = fmaf(7.f/32, v[ch][3], fmaf(5.f/32, v[ch][2], fmaf(3.f/32, v[ch][1], (1.f/32)*v[ch][0])));
                        float t = fmaf(1.f/32, v[ch][3], fmaf(3.f/32, v[ch][2], fmaf(5.f/32, v[ch][1], (7.f/32)*v[ch][0])));
                        if (cm > 0) {
                            int y = ylo + cm - 1;
                            float r = sp[ch] + t;
                            if (y == 0 || y == 63) r *= EDGE_SCALE;
                            tb[ch * 2112 + (cm - 1) * 264] = r;
                        }
                        sp[ch] = s;
                    }
                }
            }
        }
    }
    __syncthreads();

    // ---- phase 2: horizontal, aligned float4 chunks, 3 ch per thread ----
    const float4* t4 = (const float4*)tmp;   // ch stride 528, row stride 66
    {
        int yy = tid >> 6, i = tid & 63;     // 8*64 == NTHREADS
        float* op = ob + (y0 + yy) * G + i;
#pragma unroll
        for (int ch = 0; ch < 3; ch++) {
            float4 a = t4[ch * 528 + yy * 66 + i];
            float4 b = t4[ch * 528 + yy * 66 + i + 1];
            float acc = (1.f/32)*a.x + (3.f/32)*a.y + (5.f/32)*a.z + (7.f/32)*a.w
                      + (7.f/32)*b.x + (5.f/32)*b.y + (3.f/32)*b.z + (1.f/32)*b.w;
            if (i == 0 || i == 63) acc *= EDGE_SCALE;
            op[ch * (G * G)] = acc;
        }
    }
}

// ======================= S = 2 (img2 -> window 1) =======================
// Weights [1,3,3,1]/8; chunk m = rows {2m-1,2m}: s=[1,3]/8, t=[3,1]/8.
// 16 output rows per block, 3 channels. tmp: [3][16][132]; col j at +1.
__device__ void ds2_slice3(const float* __restrict__ imgb, float* __restrict__ ob,
                           int by, int bx, int y0, float* __restrict__ tmp) {
    const int tid = threadIdx.x;

    // zero pads: 3*16 = 48 rows (contiguous, stride 132) x cells {0,129}
    if (tid < 96) {
        int rs = tid >> 1, k = tid & 1;
        tmp[rs * 132 + (k ? 129 : 0)] = 0.f;
    }

    // ---- phase 1: vertical; j = tid&127 (col), h = tid>>7 (4 rows each) ----
    {
        const int j   = tid & 127;
        const int h   = tid >> 7;            // 0..3
        const int ylo = y0 + 4 * h;
        const int gx  = bx + j;
        float* tb = tmp + (4 * h) * 132 + 1 + j;   // + ch*2112 + cm*132 (imm)
        if ((unsigned)gx >= (unsigned)IMGSZ) {
#pragma unroll
            for (int ch = 0; ch < 3; ch++)
#pragma unroll
                for (int yy = 0; yy < 4; yy++) tb[ch * 2112 + yy * 132] = 0.f;
        } else {
            const int rlo = 2 * ylo - 1;
            const bool allok = (rlo >= 0) && (rlo + 9 < 128) &&
                               (by + rlo >= 0) && (by + rlo + 9 < IMGSZ);
            float sp[3] = {0.f, 0.f, 0.f};
            if (allok) {
                const float* p = imgb + (size_t)(by + rlo) * IMGSZ + gx;
#pragma unroll
                for (int cm = 0; cm <= 4; cm++) {
#pragma unroll
                    for (int ch = 0; ch < 3; ch++) {
                        const float* q = p + ch * CHSTRIDE + 2 * cm * IMGSZ;
                        float v0 = __ldg(q);
                        float v1 = __ldg(q + IMGSZ);
                        float s = fmaf(3.f/8, v1, (1.f/8)*v0);
                        float t = fmaf(1.f/8, v1, (3.f/8)*v0);
                        if (cm > 0) {
                            int y = ylo + cm - 1;
                            float r = sp[ch] + t;
                            if (y == 0 || y == 63) r *= EDGE_SCALE;
                            tb[ch * 2112 + (cm - 1) * 132] = r;
                        }
                        sp[ch] = s;
                    }
                }
            } else {
#pragma unroll
                for (int cm = 0; cm <= 4; cm++) {
                    float v[3][2];
#pragma unroll
                    for (int k = 0; k < 2; k++) {
                        int r  = 2 * (ylo + cm) - 1 + k;
                        int gy = by + r;
                        bool ok = (unsigned)r < 128u && (unsigned)gy < (unsigned)IMGSZ;
                        const float* q = imgb + (size_t)(ok ? gy : 0) * IMGSZ + gx;
#pragma unroll
                        for (int ch = 0; ch < 3; ch++)
                            v[ch][k] = ok ? __ldg(q + ch * CHSTRIDE) : 0.f;
                    }
#pragma unroll
                    for (int ch = 0; ch < 3; ch++) {
                        float s = fmaf(3.f/8, v[ch][1], (1.f/8)*v[ch][0]);
                        float t = fmaf(1.f/8, v[ch][1], (3.f/8)*v[ch][0]);
                        if (cm > 0) {
                            int y = ylo + cm - 1;
                            float r = sp[ch] + t;
                            if (y == 0 || y == 63) r *= EDGE_SCALE;
                            tb[ch * 2112 + (cm - 1) * 132] = r;
                        }
                        sp[ch] = s;
                    }
                }
            }
        }
    }
    __syncthreads();

    // ---- phase 2: horizontal, aligned float2 chunks, 3 ch per thread ----
    const float2* t2 = (const float2*)tmp;   // ch stride 1056, row stride 66
#pragma unroll
    for (int u = 0; u < 2; u++) {
        int idx = tid + u * NTHREADS;        // 16*64 = 1024
        int yy = idx >> 6, i = idx & 63;
        float* op = ob + (y0 + yy) * G + i;
#pragma unroll
        for (int ch = 0; ch < 3; ch++) {
            float2 a = t2[ch * 1056 + yy * 66 + i];
            float2 b = t2[ch * 1056 + yy * 66 + i + 1];
            float acc = (1.f/8)*a.x + (3.f/8)*a.y + (3.f/8)*b.x + (1.f/8)*b.y;
            if (i == 0 || i == 63) acc *= EDGE_SCALE;
            op[ch * (G * G)] = acc;
        }
    }
}

// Grid (832 blocks), heavy work first:
//   [0, 512)   : S=4, 8 slices x 8 rows per b (3 channels fused)
//   [512, 768) : S=2, 4 slices x 16 rows per b
//   [768, 832) : direct 64x64 zero-padded crop of img0, 3 channels
__global__ __launch_bounds__(NTHREADS, 3)
void glimpse_kernel(const float* __restrict__ img0,
                    const float* __restrict__ img2,
                    const float* __restrict__ img4,
                    const float* __restrict__ loc,
                    float* __restrict__ out) {
    extern __shared__ __align__(16) float tmp[];

    int blk = blockIdx.x;
    int sel, b, slice;
    if (blk < 512)      { sel = 0; b = blk >> 3;         slice = blk & 7; }
    else if (blk < 768) { sel = 1; b = (blk - 512) >> 2; slice = (blk - 512) & 3; }
    else                { sel = 2; b = blk - 768;        slice = 0; }

    // start index, matching jnp: trunc(0.5f * ((loc + 1.0f) * 511.0f))
    float lx = loc[2 * b + 0];
    float ly = loc[2 * b + 1];
    int sx = (int)(0.5f * ((lx + 1.0f) * 511.0f));
    int sy = (int)(0.5f * ((ly + 1.0f) * 511.0f));

    if (sel == 0) {
        const float* imgb = img4 + (size_t)b * 3 * CHSTRIDE;
        float* ob = out + (size_t)(b * 9 + 6) * (G * G);
        ds4_slice3(imgb, ob, sy - 128, sx - 128, slice * 8, tmp);
    } else if (sel == 1) {
        const float* imgb = img2 + (size_t)b * 3 * CHSTRIDE;
        float* ob = out + (size_t)(b * 9 + 3) * (G * G);
        ds2_slice3(imgb, ob, sy - 64, sx - 64, slice * 16, tmp);
    } else {
        const float* imgb = img0 + (size_t)b * 3 * CHSTRIDE;
        float* ob = out + (size_t)(b * 9 + 0) * (G * G);
        int by = sy - G / 2, bx = sx - G / 2;
#pragma unroll
        for (int u = 0; u < 8; u++) {
            int idx = threadIdx.x + u * NTHREADS;   // 4096 positions
            int y = idx >> 6, x = idx & 63;
            int gy = by + y, gx = bx + x;
            bool ok = (unsigned)gy < IMGSZ && (unsigned)gx < IMGSZ;
            const float* q = imgb + (size_t)(ok ? gy : 0) * IMGSZ + (ok ? gx : 0);
#pragma unroll
            for (int ch = 0; ch < 3; ch++)
                ob[ch * (G * G) + y * G + x] = ok ? __ldg(q + ch * CHSTRIDE) : 0.f;
        }
    }
}

extern "C" void kernel_launch(void* const* d_in, const int* in_sizes, int n_in,
                              void* d_out, int out_size) {
    const float* img0 = (const float*)d_in[0];
    const float* img2 = (const float*)d_in[1];
    const float* img4 = (const float*)d_in[2];
    const float* loc  = (const float*)d_in[3];
    float* out = (float*)d_out;

    const size_t smem = 25344;   // 3 * 8 * 264 * 4 == 3 * 16 * 132 * 4
    cudaFuncSetAttribute(glimpse_kernel,
                         cudaFuncAttributeMaxDynamicSharedMemorySize, (int)smem);
    glimpse_kernel<<<832, NTHREADS, smem>>>(img0, img2, img4, loc, out);
}